// round 8
// baseline (speedup 1.0000x reference)
#include <cuda_runtime.h>
#include <cuda_bf16.h>
#include <math.h>

// ---------------- problem constants ----------------
#define BB    32
#define HH    28
#define WW    28
#define CC    192
#define HEADS 6
#define HD    32
#define KW    3
#define K2    9
#define NTOK  (BB*HH*WW)          // 25088
#define HID   576
#define ACOLS (K2*K2*HEADS)       // 486
#define APAD  (K2*HEADS*12)       // 648; layout [i][head][12]
#define SCALE 0.17677669529663687f
#define EPSLN 1e-5f

// ---------------- scratch (static device globals; no allocs) ----------------
__device__ float g_ln1[(size_t)NTOK*CC];
__device__ float g_v  [(size_t)NTOK*CC];
__device__ float g_a  [(size_t)NTOK*APAD];   // zero-init; pad slots never written
__device__ float g_tmp[(size_t)NTOK*CC];
__device__ float g_x2 [(size_t)NTOK*CC];
__device__ float g_ln2[(size_t)NTOK*CC];
__device__ float g_h1 [(size_t)NTOK*HID];

// ---------------- LayerNorm: one warp per token ----------------
__global__ void ln_kernel(const float* __restrict__ x,
                          const float* __restrict__ g,
                          const float* __restrict__ b,
                          float* __restrict__ out)
{
    int warp = (blockIdx.x * blockDim.x + threadIdx.x) >> 5;
    int lane = threadIdx.x & 31;
    if (warp >= NTOK) return;
    const float* row = x + (size_t)warp * CC;
    float vals[6];
    float s = 0.f;
    #pragma unroll
    for (int i = 0; i < 6; i++) { vals[i] = row[lane + 32*i]; s += vals[i]; }
    #pragma unroll
    for (int o = 16; o > 0; o >>= 1) s += __shfl_xor_sync(0xffffffffu, s, o);
    float mean = s * (1.f/CC);
    float vs = 0.f;
    #pragma unroll
    for (int i = 0; i < 6; i++) { float d = vals[i]-mean; vs += d*d; }
    #pragma unroll
    for (int o = 16; o > 0; o >>= 1) vs += __shfl_xor_sync(0xffffffffu, vs, o);
    float r = rsqrtf(vs * (1.f/CC) + EPSLN);
    float* orow = out + (size_t)warp * CC;
    #pragma unroll
    for (int i = 0; i < 6; i++) {
        int c = lane + 32*i;
        orow[c] = (vals[i]-mean) * r * g[c] + b[c];
    }
}

// ---------------- TF32 tensor-core GEMM (cp.async, 2-stage, 256x64 tile) ----------------
#define SA_ST 36   // 36 % 32 == 4 -> conflict-free A fragment reads
#define SB_ST 72   // >= 64 cols, 72 % 32 == 8 -> conflict-free B fragment reads
#define SA_SZ (256*SA_ST)
#define SB_SZ (32*SB_ST)
#define STG_WORDS (SA_SZ + SB_SZ)
#define GEMM_SMEM (2*STG_WORDS*4)  // 92160 bytes

__device__ __forceinline__ void cp16(unsigned dst, const void* src) {
    asm volatile("cp.async.ca.shared.global [%0], [%1], 16;" :: "r"(dst), "l"(src));
}
__device__ __forceinline__ void cp8z(unsigned dst, const void* src, int nbytes) {
    asm volatile("cp.async.ca.shared.global [%0], [%1], 8, %2;" :: "r"(dst), "l"(src), "r"(nbytes));
}
__device__ __forceinline__ void cp_commit() {
    asm volatile("cp.async.commit_group;");
}

// remap 0..485 -> padded [i][head][12] offset: c = 81h + 9i + j -> i*72 + h*12 + j
__device__ __forceinline__ int a_remap(int c) {
    int h = c / 81;
    int r = c - 81*h;
    int i = r / 9;
    int j = r - 9*i;
    return i*72 + h*12 + j;
}

// EPI: 0 bias-only, 1 bias+gelu, 2 bias+residual, 3 bias + padded a-layout store
template<int EPI>
__global__ __launch_bounds__(256, 2)
void gemm_tf32_kernel(const float* __restrict__ A,
                      const float* __restrict__ Bw,
                      const float* __restrict__ bias,
                      const float* __restrict__ res,
                      float* __restrict__ out,
                      int Kd, int M)
{
    extern __shared__ unsigned smem[];
    const unsigned smem_base = (unsigned)__cvta_generic_to_shared(smem);

    const int tid  = threadIdx.x;
    const int lane = tid & 31;
    const int w    = tid >> 5;
    const int wr   = w & 3;
    const int wc   = w >> 2;
    const int gid  = lane >> 2;
    const int tig  = lane & 3;
    const int row0 = blockIdx.y * 256;
    const int col0 = blockIdx.x * 64;

    float acc[4][4][4];
    #pragma unroll
    for (int mt = 0; mt < 4; mt++)
        #pragma unroll
        for (int nt = 0; nt < 4; nt++)
            #pragma unroll
            for (int i = 0; i < 4; i++) acc[mt][nt][i] = 0.f;

    const int nk = Kd / 32;

    auto issue_stage = [&](int s) {
        int kb = s * 32;
        unsigned base = smem_base + (unsigned)((s & 1) * STG_WORDS * 4);
        #pragma unroll
        for (int i = 0; i < 8; i++) {
            int f = tid + 256*i;
            int r = f >> 3, kq = (f & 7) * 4;
            cp16(base + (unsigned)((r*SA_ST + kq)*4),
                 &A[(size_t)(row0 + r) * Kd + kb + kq]);
        }
        unsigned bbase = base + (unsigned)(SA_SZ*4);
        #pragma unroll
        for (int i = 0; i < 4; i++) {
            int f = tid + 256*i;
            int kr = f >> 5, c2 = f & 31;
            int col = col0 + c2*2;
            int rem = M - col;
            int nb = rem >= 2 ? 8 : (rem == 1 ? 4 : 0);
            int colc = col < M - 2 ? col : M - 2;
            cp8z(bbase + (unsigned)((kr*SB_ST + c2*2)*4),
                 &Bw[(size_t)(kb + kr) * M + colc], nb);
        }
    };

    issue_stage(0); cp_commit();
    issue_stage(1); cp_commit();

    for (int it = 0; it < nk; it++) {
        if (it + 1 < nk) asm volatile("cp.async.wait_group 1;" ::: "memory");
        else             asm volatile("cp.async.wait_group 0;" ::: "memory");
        __syncthreads();

        const unsigned* cA = (const unsigned*)smem + (it & 1) * STG_WORDS;
        const unsigned* cB = cA + SA_SZ;
        #pragma unroll
        for (int ks = 0; ks < 4; ks++) {
            const int k0 = ks * 8;
            unsigned af[4][4];
            #pragma unroll
            for (int mt = 0; mt < 4; mt++) {
                int r = wr*64 + mt*16 + gid;
                af[mt][0] = cA[ r     *SA_ST + k0 + tig    ];
                af[mt][1] = cA[(r + 8)*SA_ST + k0 + tig    ];
                af[mt][2] = cA[ r     *SA_ST + k0 + tig + 4];
                af[mt][3] = cA[(r + 8)*SA_ST + k0 + tig + 4];
            }
            unsigned bf[4][2];
            #pragma unroll
            for (int nt = 0; nt < 4; nt++) {
                int c = wc*32 + nt*8 + gid;
                bf[nt][0] = cB[(k0 + tig    )*SB_ST + c];
                bf[nt][1] = cB[(k0 + tig + 4)*SB_ST + c];
            }
            #pragma unroll
            for (int mt = 0; mt < 4; mt++)
                #pragma unroll
                for (int nt = 0; nt < 4; nt++) {
                    asm volatile(
                      "mma.sync.aligned.m16n8k8.row.col.f32.tf32.tf32.f32 "
                      "{%0,%1,%2,%3},{%4,%5,%6,%7},{%8,%9},{%0,%1,%2,%3};"
                      : "+f"(acc[mt][nt][0]), "+f"(acc[mt][nt][1]),
                        "+f"(acc[mt][nt][2]), "+f"(acc[mt][nt][3])
                      : "r"(af[mt][0]), "r"(af[mt][1]),
                        "r"(af[mt][2]), "r"(af[mt][3]),
                        "r"(bf[nt][0]), "r"(bf[nt][1]));
                }
        }
        __syncthreads();
        if (it + 2 < nk) { issue_stage(it + 2); cp_commit(); }
    }

    // epilogue
    if (EPI == 3) {
        // hoisted remap: offsets depend only on nt
        int ro[4][2];
        float2 bb[4];
        bool okc[4];
        #pragma unroll
        for (int nt = 0; nt < 4; nt++) {
            int col = col0 + wc*32 + nt*8 + tig*2;
            okc[nt] = (col < M);
            int c = okc[nt] ? col : 0;
            ro[nt][0] = a_remap(c);
            ro[nt][1] = a_remap(c + 1);
            bb[nt] = okc[nt] ? *(const float2*)&bias[c] : make_float2(0.f, 0.f);
        }
        #pragma unroll
        for (int mt = 0; mt < 4; mt++) {
            #pragma unroll
            for (int half = 0; half < 2; half++) {
                int row = row0 + wr*64 + mt*16 + gid + half*8;
                float* orow = out + (size_t)row * APAD;
                #pragma unroll
                for (int nt = 0; nt < 4; nt++) {
                    if (okc[nt]) {
                        orow[ro[nt][0]] = acc[mt][nt][half*2    ] + bb[nt].x;
                        orow[ro[nt][1]] = acc[mt][nt][half*2 + 1] + bb[nt].y;
                    }
                }
            }
        }
    } else {
        #pragma unroll
        for (int mt = 0; mt < 4; mt++) {
            #pragma unroll
            for (int nt = 0; nt < 4; nt++) {
                int r0  = row0 + wr*64 + mt*16 + gid;
                int col = col0 + wc*32 + nt*8 + tig*2;
                if (col < M) {
                    float2 bb = make_float2(0.f, 0.f);
                    if (bias) bb = *(const float2*)&bias[col];
                    #pragma unroll
                    for (int half = 0; half < 2; half++) {
                        int row = r0 + half*8;
                        float2 vv;
                        vv.x = acc[mt][nt][half*2    ] + bb.x;
                        vv.y = acc[mt][nt][half*2 + 1] + bb.y;
                        if (EPI == 1) {
                            vv.x = 0.5f * vv.x * (1.0f + erff(vv.x * 0.70710678118654752f));
                            vv.y = 0.5f * vv.y * (1.0f + erff(vv.y * 0.70710678118654752f));
                        } else if (EPI == 2) {
                            float2 rr = *(const float2*)&res[(size_t)row * M + col];
                            vv.x += rr.x; vv.y += rr.y;
                        }
                        *(float2*)&out[(size_t)row * M + col] = vv;
                    }
                }
            }
        }
    }
}

// ---------------- fused outlook attention + fold ----------------
// a layout: [t][i][head][12]. Warp-cooperative chunk load + in-place softmax.
#define PR_WARP APAD   // 648 floats per warp

__global__ void attn_fold_kernel(const float* __restrict__ a,
                                 const float* __restrict__ v,
                                 float* __restrict__ tmp)
{
    __shared__ float probs[8][PR_WARP];
    int warp = threadIdx.x >> 5;
    int lane = threadIdx.x & 31;
    int t = blockIdx.x * 8 + warp;
    int b  = t / (HH*WW);
    int pq = t % (HH*WW);
    int p = pq / WW, q = pq % WW;

    // ---- phase A1: cooperative load of 9 source chunks (72 floats each) ----
    float4* pf4 = (float4*)&probs[warp][0];   // 162 float4
    #pragma unroll
    for (int it2 = 0; it2 < 6; it2++) {
        int e = lane + it2*32;
        if (e < 162) {
            int r = e / 18;            // window slot i
            int s = e - r*18;          // float4 within chunk
            int di = r / 3, dj = r - 3*(r/3);
            int tp = p + 1 - di, tq = q + 1 - dj;
            float4 val = make_float4(0.f, 0.f, 0.f, 0.f);
            if ((unsigned)tp < (unsigned)HH && (unsigned)tq < (unsigned)WW) {
                int ts = (b*HH + tp) * WW + tq;
                val = *(const float4*)(a + (size_t)ts * APAD + r*72 + s*4);
            }
            pf4[e] = val;
        }
    }
    __syncwarp();

    // ---- phase A2: in-place softmax of 54 rows (2 per lane, lanes<27) ----
    if (lane < 27) {
        #pragma unroll
        for (int rep = 0; rep < 2; rep++) {
            int rr = lane + rep*27;    // 0..53
            int i = rr / 6, h = rr - 6*i;
            int di = i / 3, dj = i - 3*(i/3);
            int tp = p + 1 - di, tq = q + 1 - dj;
            if ((unsigned)tp < (unsigned)HH && (unsigned)tq < (unsigned)WW) {
                float* rowp = &probs[warp][i*72 + h*12];
                float4 x0 = *(const float4*)rowp;
                float4 x1 = *(const float4*)(rowp + 4);
                float  x8 = rowp[8];
                float vv[K2] = {x0.x, x0.y, x0.z, x0.w, x1.x, x1.y, x1.z, x1.w, x8};
                float mx = -INFINITY;
                #pragma unroll
                for (int j = 0; j < K2; j++) { vv[j] *= SCALE; mx = fmaxf(mx, vv[j]); }
                float s = 0.f;
                #pragma unroll
                for (int j = 0; j < K2; j++) { vv[j] = __expf(vv[j] - mx); s += vv[j]; }
                float inv = __fdividef(1.f, s);
                *(float4*)rowp       = make_float4(vv[0]*inv, vv[1]*inv, vv[2]*inv, vv[3]*inv);
                *(float4*)(rowp + 4) = make_float4(vv[4]*inv, vv[5]*inv, vv[6]*inv, vv[7]*inv);
                rowp[8] = vv[8]*inv;
            }
            // invalid rows: already all-zero from the load — nothing to do
        }
    }
    __syncwarp();

    // ---- phase B: window gather, separable index precompute ----
    int rowbase[5], coloff[5];
    unsigned rmask = 0, cmask = 0;
    #pragma unroll
    for (int d = 0; d < 5; d++) {
        int vp = p + d - 2, vq = q + d - 2;
        bool rok = (unsigned)vp < (unsigned)HH;
        bool cok = (unsigned)vq < (unsigned)WW;
        rowbase[d] = rok ? ((b*HH + vp) * WW) * CC : 0;
        coloff[d]  = cok ? vq * CC : 0;
        if (rok) rmask |= (1u << d);
        if (cok) cmask |= (1u << d);
    }

    for (int head = 0; head < HEADS; head++) {
        const int ch = head*HD + lane;
        float vr[25];
        #pragma unroll
        for (int dp = 0; dp < 5; dp++) {
            #pragma unroll
            for (int dq = 0; dq < 5; dq++) {
                bool ok = ((rmask >> dp) & 1u) && ((cmask >> dq) & 1u);
                vr[dp*5 + dq] = ok ? v[(size_t)(rowbase[dp] + coloff[dq] + ch)] : 0.f;
            }
        }
        const float* prh = &probs[warp][head*12];
        float acc = 0.f;
        #pragma unroll
        for (int i = 0; i < K2; i++) {
            int di = i / KW, dj = i - di*KW;
            const float* rowp = prh + i*72;
            float4 r0 = *(const float4*)rowp;
            float4 r1 = *(const float4*)(rowp + 4);
            float  r2 = rowp[8];
            float pr[K2] = {r0.x, r0.y, r0.z, r0.w, r1.x, r1.y, r1.z, r1.w, r2};
            const float* vb = &vr[(2 - di)*5 + (2 - dj)];
            #pragma unroll
            for (int j = 0; j < K2; j++) {
                int ei = j / KW, ej = j - ei*KW;
                acc = fmaf(pr[j], vb[ei*5 + ej], acc);
            }
        }
        tmp[(size_t)t * CC + ch] = acc;
    }
}

// ---------------- launcher ----------------
extern "C" void kernel_launch(void* const* d_in, const int* in_sizes, int n_in,
                              void* d_out, int out_size)
{
    const float* x     = (const float*)d_in[0];
    const float* ln1_g = (const float*)d_in[1];
    const float* ln1_b = (const float*)d_in[2];
    const float* Wv    = (const float*)d_in[3];
    const float* Wa    = (const float*)d_in[4];
    const float* ba    = (const float*)d_in[5];
    const float* Wp    = (const float*)d_in[6];
    const float* bp    = (const float*)d_in[7];
    const float* ln2_g = (const float*)d_in[8];
    const float* ln2_b = (const float*)d_in[9];
    const float* W1    = (const float*)d_in[10];
    const float* b1    = (const float*)d_in[11];
    const float* W2    = (const float*)d_in[12];
    const float* b2    = (const float*)d_in[13];
    float* out = (float*)d_out;

    float *p_ln1, *p_v, *p_a, *p_tmp, *p_x2, *p_ln2, *p_h1;
    cudaGetSymbolAddress((void**)&p_ln1, g_ln1);
    cudaGetSymbolAddress((void**)&p_v,   g_v);
    cudaGetSymbolAddress((void**)&p_a,   g_a);
    cudaGetSymbolAddress((void**)&p_tmp, g_tmp);
    cudaGetSymbolAddress((void**)&p_x2,  g_x2);
    cudaGetSymbolAddress((void**)&p_ln2, g_ln2);
    cudaGetSymbolAddress((void**)&p_h1,  g_h1);

    cudaFuncSetAttribute(gemm_tf32_kernel<0>, cudaFuncAttributeMaxDynamicSharedMemorySize, GEMM_SMEM);
    cudaFuncSetAttribute(gemm_tf32_kernel<1>, cudaFuncAttributeMaxDynamicSharedMemorySize, GEMM_SMEM);
    cudaFuncSetAttribute(gemm_tf32_kernel<2>, cudaFuncAttributeMaxDynamicSharedMemorySize, GEMM_SMEM);
    cudaFuncSetAttribute(gemm_tf32_kernel<3>, cudaFuncAttributeMaxDynamicSharedMemorySize, GEMM_SMEM);

    const int RB = NTOK / 256;   // 98

    ln_kernel<<<NTOK/8, 256>>>(x, ln1_g, ln1_b, p_ln1);
    gemm_tf32_kernel<0><<<dim3((CC+63)/64, RB), 256, GEMM_SMEM>>>(p_ln1, Wv, nullptr, nullptr, p_v, CC, CC);
    gemm_tf32_kernel<3><<<dim3((ACOLS+63)/64, RB), 256, GEMM_SMEM>>>(p_ln1, Wa, ba, nullptr, p_a, CC, ACOLS);
    attn_fold_kernel<<<NTOK/8, 256>>>(p_a, p_v, p_tmp);
    gemm_tf32_kernel<2><<<dim3((CC+63)/64, RB), 256, GEMM_SMEM>>>(p_tmp, Wp, bp, x, p_x2, CC, CC);
    ln_kernel<<<NTOK/8, 256>>>(p_x2, ln2_g, ln2_b, p_ln2);
    gemm_tf32_kernel<1><<<dim3((HID+63)/64, RB), 256, GEMM_SMEM>>>(p_ln2, W1, b1, nullptr, p_h1, CC, HID);
    gemm_tf32_kernel<2><<<dim3((CC+63)/64, RB), 256, GEMM_SMEM>>>(p_h1, W2, b2, p_x2, out, HID, CC);
}

// round 9
// speedup vs baseline: 1.3029x; 1.3029x over previous
#include <cuda_runtime.h>
#include <cuda_fp16.h>
#include <math.h>

// ---------------- problem constants ----------------
#define BB    32
#define HH    28
#define WW    28
#define CC    192
#define HEADS 6
#define HD    32
#define KW    3
#define K2    9
#define NTOK  (BB*HH*WW)          // 25088
#define HID   576
#define ACOLS (K2*K2*HEADS)       // 486
#define SCALE 0.17677669529663687f
#define EPSLN 1e-5f

// weight-half pool offsets
#define WOFF_V  0
#define WOFF_A  (WOFF_V + CC*CC)        // 36864
#define WOFF_P  (WOFF_A + CC*ACOLS)     // 130176
#define WOFF_1  (WOFF_P + CC*CC)        // 167040
#define WOFF_2  (WOFF_1 + CC*HID)       // 277632
#define WTOT    (WOFF_2 + HID*CC)       // 388224

// ---------------- scratch (static device globals; no allocs) ----------------
__device__ __half g_wh [WTOT];
__device__ __half g_ln1[(size_t)NTOK*CC];
__device__ float  g_v  [(size_t)NTOK*CC];
__device__ float  g_a  [(size_t)NTOK*ACOLS];
__device__ __half g_tmp[(size_t)NTOK*CC];
__device__ float  g_x2 [(size_t)NTOK*CC];
__device__ __half g_ln2[(size_t)NTOK*CC];
__device__ __half g_h1 [(size_t)NTOK*HID];

// ---------------- weight fp32 -> fp16 ----------------
__global__ void wconv_kernel(const float* __restrict__ Wv, const float* __restrict__ Wa,
                             const float* __restrict__ Wp, const float* __restrict__ W1,
                             const float* __restrict__ W2, __half* __restrict__ out)
{
    int i = blockIdx.x * 256 + threadIdx.x;
    if (i >= WTOT) return;
    const float* src; int off;
    if      (i < WOFF_A) { src = Wv; off = i; }
    else if (i < WOFF_P) { src = Wa; off = i - WOFF_A; }
    else if (i < WOFF_1) { src = Wp; off = i - WOFF_P; }
    else if (i < WOFF_2) { src = W1; off = i - WOFF_1; }
    else                 { src = W2; off = i - WOFF_2; }
    out[i] = __float2half_rn(src[off]);
}

// ---------------- LayerNorm: one warp per token, half output ----------------
__global__ void ln_kernel(const float* __restrict__ x,
                          const float* __restrict__ g,
                          const float* __restrict__ b,
                          __half* __restrict__ out)
{
    int warp = (blockIdx.x * blockDim.x + threadIdx.x) >> 5;
    int lane = threadIdx.x & 31;
    if (warp >= NTOK) return;
    const float* row = x + (size_t)warp * CC;
    float vals[6];
    float s = 0.f;
    #pragma unroll
    for (int i = 0; i < 6; i++) { vals[i] = row[lane + 32*i]; s += vals[i]; }
    #pragma unroll
    for (int o = 16; o > 0; o >>= 1) s += __shfl_xor_sync(0xffffffffu, s, o);
    float mean = s * (1.f/CC);
    float vs = 0.f;
    #pragma unroll
    for (int i = 0; i < 6; i++) { float d = vals[i]-mean; vs += d*d; }
    #pragma unroll
    for (int o = 16; o > 0; o >>= 1) vs += __shfl_xor_sync(0xffffffffu, vs, o);
    float r = rsqrtf(vs * (1.f/CC) + EPSLN);
    __half* orow = out + (size_t)warp * CC;
    #pragma unroll
    for (int i = 0; i < 6; i++) {
        int c = lane + 32*i;
        orow[c] = __float2half_rn((vals[i]-mean) * r * g[c] + b[c]);
    }
}

// ---------------- FP16 tensor-core GEMM (cp.async, 2-stage, 256x64 tile) ----------------
#define SA_ST 40   // halves; word stride 20 -> conflict-free A fragment LDS.32
#define SB_ST 72   // halves; word stride 36 -> conflict-free B fragment LDS.16
#define SA_SZ (256*SA_ST)            // halves per A stage (10240)
#define SB_SZ (32*SB_ST)             // halves per B stage (2304)
#define STG_H (SA_SZ + SB_SZ)        // 12544 halves / stage
#define GEMM_SMEM (2*STG_H*2)        // 50176 bytes

__device__ __forceinline__ void cp16(unsigned dst, const void* src) {
    asm volatile("cp.async.ca.shared.global [%0], [%1], 16;" :: "r"(dst), "l"(src));
}
__device__ __forceinline__ void cp4z(unsigned dst, const void* src, int nbytes) {
    asm volatile("cp.async.ca.shared.global [%0], [%1], 4, %2;" :: "r"(dst), "l"(src), "r"(nbytes));
}
__device__ __forceinline__ void cp_commit() {
    asm volatile("cp.async.commit_group;");
}

// EPI: 0 bias(optional) float out, 1 bias+gelu half out, 2 bias+residual float out
template<int EPI, typename OutT>
__global__ __launch_bounds__(256, 2)
void gemm_f16_kernel(const __half* __restrict__ A,
                     const __half* __restrict__ Bw,
                     const float* __restrict__ bias,
                     const float* __restrict__ res,
                     OutT* __restrict__ out,
                     int Kd, int M)
{
    extern __shared__ __half smem[];
    const unsigned smem_base = (unsigned)__cvta_generic_to_shared(smem);
    const unsigned short* smem_us = (const unsigned short*)smem;

    const int tid  = threadIdx.x;
    const int lane = tid & 31;
    const int w    = tid >> 5;
    const int wr   = w & 3;        // 64 rows each
    const int wc   = w >> 2;       // 32 cols each
    const int gid  = lane >> 2;
    const int tig  = lane & 3;
    const int row0 = blockIdx.y * 256;
    const int col0 = blockIdx.x * 64;

    float acc[4][4][4];
    #pragma unroll
    for (int mt = 0; mt < 4; mt++)
        #pragma unroll
        for (int nt = 0; nt < 4; nt++)
            #pragma unroll
            for (int i = 0; i < 4; i++) acc[mt][nt][i] = 0.f;

    const int nk = Kd / 32;

    auto issue_stage = [&](int s) {
        int kb = s * 32;
        unsigned base = smem_base + (unsigned)((s & 1) * STG_H * 2);
        // A: 256 rows x 32 halves, 16B chunks
        #pragma unroll
        for (int i = 0; i < 4; i++) {
            int f = tid + 256*i;
            int r = f >> 2, kq = (f & 3) * 8;
            cp16(base + (unsigned)((r*SA_ST + kq)*2),
                 &A[(size_t)(row0 + r) * Kd + kb + kq]);
        }
        // B: 32 k-rows x 64 cols halves, 4B chunks (handles M=486 alignment)
        unsigned bbase = base + (unsigned)(SA_SZ*2);
        #pragma unroll
        for (int i = 0; i < 4; i++) {
            int f = tid + 256*i;
            int kr = f >> 5, c2 = (f & 31) * 2;
            int col = col0 + c2;
            int nb = (col + 1 < M) ? 4 : ((col < M) ? 2 : 0);
            int colc = (col + 1 < M) ? col : (M - 2);
            cp4z(bbase + (unsigned)((kr*SB_ST + c2)*2),
                 &Bw[(size_t)(kb + kr) * M + colc], nb);
        }
    };

    issue_stage(0); cp_commit();
    issue_stage(1); cp_commit();

    for (int it = 0; it < nk; it++) {
        if (it + 1 < nk) asm volatile("cp.async.wait_group 1;" ::: "memory");
        else             asm volatile("cp.async.wait_group 0;" ::: "memory");
        __syncthreads();

        const unsigned short* cA = smem_us + (it & 1) * STG_H;
        const unsigned short* cB = cA + SA_SZ;
        #pragma unroll
        for (int ks = 0; ks < 2; ks++) {
            const int k0 = ks * 16;
            unsigned af[4][4];
            #pragma unroll
            for (int mt = 0; mt < 4; mt++) {
                int r = wr*64 + mt*16 + gid;
                af[mt][0] = *(const unsigned*)&cA[ r     *SA_ST + k0 + tig*2    ];
                af[mt][1] = *(const unsigned*)&cA[(r + 8)*SA_ST + k0 + tig*2    ];
                af[mt][2] = *(const unsigned*)&cA[ r     *SA_ST + k0 + tig*2 + 8];
                af[mt][3] = *(const unsigned*)&cA[(r + 8)*SA_ST + k0 + tig*2 + 8];
            }
            unsigned bf[4][2];
            #pragma unroll
            for (int nt = 0; nt < 4; nt++) {
                int c = wc*32 + nt*8 + gid;
                unsigned s0 = cB[(k0 + tig*2    )*SB_ST + c];
                unsigned s1 = cB[(k0 + tig*2 + 1)*SB_ST + c];
                unsigned s2 = cB[(k0 + tig*2 + 8)*SB_ST + c];
                unsigned s3 = cB[(k0 + tig*2 + 9)*SB_ST + c];
                bf[nt][0] = s0 | (s1 << 16);
                bf[nt][1] = s2 | (s3 << 16);
            }
            #pragma unroll
            for (int mt = 0; mt < 4; mt++)
                #pragma unroll
                for (int nt = 0; nt < 4; nt++) {
                    asm volatile(
                      "mma.sync.aligned.m16n8k16.row.col.f32.f16.f16.f32 "
                      "{%0,%1,%2,%3},{%4,%5,%6,%7},{%8,%9},{%0,%1,%2,%3};"
                      : "+f"(acc[mt][nt][0]), "+f"(acc[mt][nt][1]),
                        "+f"(acc[mt][nt][2]), "+f"(acc[mt][nt][3])
                      : "r"(af[mt][0]), "r"(af[mt][1]),
                        "r"(af[mt][2]), "r"(af[mt][3]),
                        "r"(bf[nt][0]), "r"(bf[nt][1]));
                }
        }
        __syncthreads();
        if (it + 2 < nk) { issue_stage(it + 2); cp_commit(); }
    }

    // epilogue
    #pragma unroll
    for (int mt = 0; mt < 4; mt++) {
        #pragma unroll
        for (int nt = 0; nt < 4; nt++) {
            int r0  = row0 + wr*64 + mt*16 + gid;
            int col = col0 + wc*32 + nt*8 + tig*2;
            if (col < M) {
                float2 bb = make_float2(0.f, 0.f);
                if (bias) bb = *(const float2*)&bias[col];
                #pragma unroll
                for (int half_i = 0; half_i < 2; half_i++) {
                    int row = r0 + half_i*8;
                    float vx = acc[mt][nt][half_i*2    ] + bb.x;
                    float vy = acc[mt][nt][half_i*2 + 1] + bb.y;
                    if (EPI == 1) {
                        vx = 0.5f * vx * (1.0f + erff(vx * 0.70710678118654752f));
                        vy = 0.5f * vy * (1.0f + erff(vy * 0.70710678118654752f));
                        *(__half2*)&out[(size_t)row * M + col] = __floats2half2_rn(vx, vy);
                    } else if (EPI == 2) {
                        float2 rr = *(const float2*)&res[(size_t)row * M + col];
                        float2 vv = make_float2(vx + rr.x, vy + rr.y);
                        *(float2*)&((float*)out)[(size_t)row * M + col] = vv;
                    } else {
                        float2 vv = make_float2(vx, vy);
                        *(float2*)&((float*)out)[(size_t)row * M + col] = vv;
                    }
                }
            }
        }
    }
}

// ---------------- fused outlook attention + fold (Round-6 form, half tmp) ----------------
#define PR_ROW 12
#define PR_HEAD (K2*PR_ROW)            // 108
#define PR_WARP (HEADS*PR_HEAD)        // 648

__global__ void attn_fold_kernel(const float* __restrict__ a,
                                 const float* __restrict__ v,
                                 __half* __restrict__ tmp)
{
    __shared__ float probs[8][PR_WARP];
    int warp = threadIdx.x >> 5;
    int lane = threadIdx.x & 31;
    int t = blockIdx.x * 8 + warp;
    int b  = t / (HH*WW);
    int pq = t % (HH*WW);
    int p = pq / WW, q = pq % WW;

    // ---- phase A: 54 softmax rows over 27 lanes (2 each) ----
    if (lane < 27) {
        #pragma unroll
        for (int rep = 0; rep < 2; rep++) {
            int rr = lane + rep*27;
            int head = rr / K2;
            int i    = rr - head*K2;
            int di = i / KW, dj = i - di*KW;
            int tp = p + 1 - di, tq = q + 1 - dj;
            float* dst = &probs[warp][head*PR_HEAD + i*PR_ROW];
            if ((unsigned)tp < (unsigned)HH && (unsigned)tq < (unsigned)WW) {
                int ts = (b*HH + tp) * WW + tq;
                const float* ar = a + (size_t)ts * ACOLS + head*81 + i*K2;
                float vv[K2];
                float mx = -INFINITY;
                #pragma unroll
                for (int j = 0; j < K2; j++) { vv[j] = ar[j] * SCALE; mx = fmaxf(mx, vv[j]); }
                float s = 0.f;
                #pragma unroll
                for (int j = 0; j < K2; j++) { vv[j] = __expf(vv[j] - mx); s += vv[j]; }
                float inv = __fdividef(1.f, s);
                #pragma unroll
                for (int j = 0; j < K2; j++) dst[j] = vv[j] * inv;
            } else {
                #pragma unroll
                for (int j = 0; j < K2; j++) dst[j] = 0.f;
            }
        }
    }
    __syncwarp();

    // ---- phase B: window gather ----
    int rowbase[5], coloff[5];
    unsigned rmask = 0, cmask = 0;
    #pragma unroll
    for (int d = 0; d < 5; d++) {
        int vp = p + d - 2, vq = q + d - 2;
        bool rok = (unsigned)vp < (unsigned)HH;
        bool cok = (unsigned)vq < (unsigned)WW;
        rowbase[d] = rok ? ((b*HH + vp) * WW) * CC : 0;
        coloff[d]  = cok ? vq * CC : 0;
        if (rok) rmask |= (1u << d);
        if (cok) cmask |= (1u << d);
    }

    for (int head = 0; head < HEADS; head++) {
        const int ch = head*HD + lane;
        float vr[25];
        #pragma unroll
        for (int dp = 0; dp < 5; dp++) {
            #pragma unroll
            for (int dq = 0; dq < 5; dq++) {
                bool ok = ((rmask >> dp) & 1u) && ((cmask >> dq) & 1u);
                vr[dp*5 + dq] = ok ? v[(size_t)(rowbase[dp] + coloff[dq] + ch)] : 0.f;
            }
        }
        const float* prh = &probs[warp][head*PR_HEAD];
        float acc = 0.f;
        #pragma unroll
        for (int i = 0; i < K2; i++) {
            int di = i / KW, dj = i - di*KW;
            const float4* rp = (const float4*)(prh + i*PR_ROW);
            float4 r0 = rp[0], r1 = rp[1];
            float  r2 = prh[i*PR_ROW + 8];
            float pr[K2] = {r0.x, r0.y, r0.z, r0.w, r1.x, r1.y, r1.z, r1.w, r2};
            const float* vb = &vr[(2 - di)*5 + (2 - dj)];
            #pragma unroll
            for (int j = 0; j < K2; j++) {
                int ei = j / KW, ej = j - ei*KW;
                acc = fmaf(pr[j], vb[ei*5 + ej], acc);
            }
        }
        tmp[(size_t)t * CC + ch] = __float2half_rn(acc);
    }
}

// ---------------- launcher ----------------
extern "C" void kernel_launch(void* const* d_in, const int* in_sizes, int n_in,
                              void* d_out, int out_size)
{
    const float* x     = (const float*)d_in[0];
    const float* ln1_g = (const float*)d_in[1];
    const float* ln1_b = (const float*)d_in[2];
    const float* Wv    = (const float*)d_in[3];
    const float* Wa    = (const float*)d_in[4];
    const float* ba    = (const float*)d_in[5];
    const float* Wp    = (const float*)d_in[6];
    const float* bp    = (const float*)d_in[7];
    const float* ln2_g = (const float*)d_in[8];
    const float* ln2_b = (const float*)d_in[9];
    const float* W1    = (const float*)d_in[10];
    const float* b1    = (const float*)d_in[11];
    const float* W2    = (const float*)d_in[12];
    const float* b2    = (const float*)d_in[13];
    float* out = (float*)d_out;

    __half *p_wh, *p_ln1, *p_tmp, *p_ln2, *p_h1;
    float  *p_v, *p_a, *p_x2;
    cudaGetSymbolAddress((void**)&p_wh,  g_wh);
    cudaGetSymbolAddress((void**)&p_ln1, g_ln1);
    cudaGetSymbolAddress((void**)&p_v,   g_v);
    cudaGetSymbolAddress((void**)&p_a,   g_a);
    cudaGetSymbolAddress((void**)&p_tmp, g_tmp);
    cudaGetSymbolAddress((void**)&p_x2,  g_x2);
    cudaGetSymbolAddress((void**)&p_ln2, g_ln2);
    cudaGetSymbolAddress((void**)&p_h1,  g_h1);

    cudaFuncSetAttribute((const void*)gemm_f16_kernel<0,float>,  cudaFuncAttributeMaxDynamicSharedMemorySize, GEMM_SMEM);
    cudaFuncSetAttribute((const void*)gemm_f16_kernel<1,__half>, cudaFuncAttributeMaxDynamicSharedMemorySize, GEMM_SMEM);
    cudaFuncSetAttribute((const void*)gemm_f16_kernel<2,float>,  cudaFuncAttributeMaxDynamicSharedMemorySize, GEMM_SMEM);

    const int RB = NTOK / 256;   // 98

    wconv_kernel<<<(WTOT + 255)/256, 256>>>(Wv, Wa, Wp, W1, W2, p_wh);
    ln_kernel<<<NTOK/8, 256>>>(x, ln1_g, ln1_b, p_ln1);
    gemm_f16_kernel<0,float><<<dim3((CC+63)/64, RB), 256, GEMM_SMEM>>>(p_ln1, p_wh + WOFF_V, nullptr, nullptr, p_v, CC, CC);
    gemm_f16_kernel<0,float><<<dim3((ACOLS+63)/64, RB), 256, GEMM_SMEM>>>(p_ln1, p_wh + WOFF_A, ba, nullptr, p_a, CC, ACOLS);
    attn_fold_kernel<<<NTOK/8, 256>>>(p_a, p_v, p_tmp);
    gemm_f16_kernel<2,float><<<dim3((CC+63)/64, RB), 256, GEMM_SMEM>>>(p_tmp, p_wh + WOFF_P, bp, x, p_x2, CC, CC);
    ln_kernel<<<NTOK/8, 256>>>(p_x2, ln2_g, ln2_b, p_ln2);
    gemm_f16_kernel<1,__half><<<dim3((HID+63)/64, RB), 256, GEMM_SMEM>>>(p_ln2, p_wh + WOFF_1, b1, nullptr, p_h1, CC, HID);
    gemm_f16_kernel<2,float><<<dim3((CC+63)/64, RB), 256, GEMM_SMEM>>>(p_h1, p_wh + WOFF_2, b2, p_x2, out, HID, CC);
}

// round 10
// speedup vs baseline: 1.3507x; 1.0367x over previous
#include <cuda_runtime.h>
#include <cuda_fp16.h>
#include <math.h>

// ---------------- problem constants ----------------
#define BB    32
#define HH    28
#define WW    28
#define CC    192
#define HEADS 6
#define HD    32
#define KW    3
#define K2    9
#define NTOK  (BB*HH*WW)          // 25088
#define HID   576
#define ACOLS (K2*K2*HEADS)       // 486
#define MVA   (CC + ACOLS)        // 678 fused V|A output cols
#define MVA_PAD 704
#define SCALE 0.17677669529663687f
#define EPSLN 1e-5f

// transposed-weight pool (halves), layout [M][K]
#define WOFF_VA 0
#define WOFF_P  (MVA_PAD*CC)              // 135168
#define WOFF_1  (WOFF_P + CC*CC)          // 172032
#define WOFF_2  (WOFF_1 + HID*CC)         // 282624
#define WTOT    (WOFF_2 + CC*HID)         // 393216
#define N_WCONV (CC*MVA + CC*CC + CC*HID + HID*CC)  // 388224 real elements

// ---------------- scratch (static device globals; no allocs) ----------------
__device__ __half g_wh [WTOT];            // zero-init; VA pad rows never written
__device__ float  g_bva[MVA_PAD];
__device__ __half g_ln1[(size_t)NTOK*CC];
__device__ float  g_va [(size_t)NTOK*MVA];
__device__ __half g_tmp[(size_t)NTOK*CC];
__device__ float  g_x2 [(size_t)NTOK*CC];
__device__ __half g_ln2[(size_t)NTOK*CC];
__device__ __half g_h1 [(size_t)NTOK*HID];

// ---------------- weight fp32 -> fp16 transpose pack ----------------
__global__ void wconv_kernel(const float* __restrict__ Wv, const float* __restrict__ Wa,
                             const float* __restrict__ Wp, const float* __restrict__ W1,
                             const float* __restrict__ W2, __half* __restrict__ out)
{
    int i = blockIdx.x * 256 + threadIdx.x;
    if (i >= N_WCONV) return;
    const int SZ_VA = CC*MVA;       // 130176
    const int SZ_P  = CC*CC;        // 36864
    const int SZ_1  = CC*HID;       // 110592
    if (i < SZ_VA) {
        int m = i / CC, k = i - m*CC;         // m in [0,678)
        float v = (m < CC) ? Wv[k*CC + m] : Wa[k*ACOLS + (m - CC)];
        out[WOFF_VA + m*CC + k] = __float2half_rn(v);
    } else if (i < SZ_VA + SZ_P) {
        int e = i - SZ_VA;
        int m = e / CC, k = e - m*CC;
        out[WOFF_P + m*CC + k] = __float2half_rn(Wp[k*CC + m]);
    } else if (i < SZ_VA + SZ_P + SZ_1) {
        int e = i - SZ_VA - SZ_P;
        int m = e / CC, k = e - m*CC;         // m in [0,576)
        out[WOFF_1 + m*CC + k] = __float2half_rn(W1[k*HID + m]);
    } else {
        int e = i - SZ_VA - SZ_P - SZ_1;
        int m = e / HID, k = e - m*HID;       // m in [0,192), k in [0,576)
        out[WOFF_2 + m*HID + k] = __float2half_rn(W2[k*CC + m]);
    }
}

__global__ void bias_fuse_kernel(const float* __restrict__ ba, float* __restrict__ bva)
{
    int i = blockIdx.x * 256 + threadIdx.x;
    if (i < MVA_PAD) bva[i] = (i >= CC && i < MVA) ? ba[i - CC] : 0.f;
}

// ---------------- LayerNorm: one warp per token, half output ----------------
__global__ void ln_kernel(const float* __restrict__ x,
                          const float* __restrict__ g,
                          const float* __restrict__ b,
                          __half* __restrict__ out)
{
    int warp = (blockIdx.x * blockDim.x + threadIdx.x) >> 5;
    int lane = threadIdx.x & 31;
    if (warp >= NTOK) return;
    const float* row = x + (size_t)warp * CC;
    float vals[6];
    float s = 0.f;
    #pragma unroll
    for (int i = 0; i < 6; i++) { vals[i] = row[lane + 32*i]; s += vals[i]; }
    #pragma unroll
    for (int o = 16; o > 0; o >>= 1) s += __shfl_xor_sync(0xffffffffu, s, o);
    float mean = s * (1.f/CC);
    float vs = 0.f;
    #pragma unroll
    for (int i = 0; i < 6; i++) { float d = vals[i]-mean; vs += d*d; }
    #pragma unroll
    for (int o = 16; o > 0; o >>= 1) vs += __shfl_xor_sync(0xffffffffu, vs, o);
    float r = rsqrtf(vs * (1.f/CC) + EPSLN);
    __half* orow = out + (size_t)warp * CC;
    #pragma unroll
    for (int i = 0; i < 6; i++) {
        int c = lane + 32*i;
        orow[c] = __float2half_rn((vals[i]-mean) * r * g[c] + b[c]);
    }
}

// ---------------- FP16 GEMM: A[N,K] @ B^T (B stored [M,K]); 3-stage; 256x64 tile ----
#define SA_ST 40                      // halves; row pad -> conflict-free LDS.32
#define SB_ST 40
#define SA_SZ (256*SA_ST)             // 10240 halves / stage
#define SB_SZ (64*SB_ST)              // 2560 halves / stage
#define STG_H (SA_SZ + SB_SZ)         // 12800
#define GEMM_SMEM (3*STG_H*2)         // 76800 bytes

__device__ __forceinline__ void cp16(unsigned dst, const void* src) {
    asm volatile("cp.async.ca.shared.global [%0], [%1], 16;" :: "r"(dst), "l"(src));
}
__device__ __forceinline__ void cp_commit() {
    asm volatile("cp.async.commit_group;");
}

// EPI: 0 bias float out, 1 bias+gelu half out, 2 bias+residual float out
template<int EPI, typename OutT>
__global__ __launch_bounds__(256, 2)
void gemm_f16_kernel(const __half* __restrict__ A,
                     const __half* __restrict__ Bt,   // [M_pad, Kd]
                     const float* __restrict__ bias,
                     const float* __restrict__ res,
                     OutT* __restrict__ out,
                     int Kd, int M)
{
    extern __shared__ __half smem[];
    const unsigned smem_base = (unsigned)__cvta_generic_to_shared(smem);
    const unsigned short* smem_us = (const unsigned short*)smem;

    const int tid  = threadIdx.x;
    const int lane = tid & 31;
    const int w    = tid >> 5;
    const int wr   = w & 3;        // 64 rows each
    const int wc   = w >> 2;       // 32 cols each
    const int gid  = lane >> 2;
    const int tig  = lane & 3;
    const int row0 = blockIdx.y * 256;
    const int col0 = blockIdx.x * 64;

    float acc[4][4][4];
    #pragma unroll
    for (int mt = 0; mt < 4; mt++)
        #pragma unroll
        for (int nt = 0; nt < 4; nt++)
            #pragma unroll
            for (int i = 0; i < 4; i++) acc[mt][nt][i] = 0.f;

    const int nk = Kd / 32;

    auto issue_stage = [&](int s) {
        int kb = s * 32;
        unsigned base = smem_base + (unsigned)((s % 3) * STG_H * 2);
        // A: 256 rows x 32 halves
        #pragma unroll
        for (int i = 0; i < 4; i++) {
            int f = tid + 256*i;
            int r = f >> 2, kq = (f & 3) * 8;
            cp16(base + (unsigned)((r*SA_ST + kq)*2),
                 &A[(size_t)(row0 + r) * Kd + kb + kq]);
        }
        // B^T: 64 rows (out cols) x 32 halves
        unsigned bbase = base + (unsigned)(SA_SZ*2);
        {
            int r = tid >> 2, kq = (tid & 3) * 8;
            cp16(bbase + (unsigned)((r*SB_ST + kq)*2),
                 &Bt[(size_t)(col0 + r) * Kd + kb + kq]);
        }
    };

    issue_stage(0); cp_commit();
    issue_stage(1); cp_commit();

    for (int it = 0; it < nk; it++) {
        if (it + 1 < nk) asm volatile("cp.async.wait_group 1;" ::: "memory");
        else             asm volatile("cp.async.wait_group 0;" ::: "memory");
        __syncthreads();
        if (it + 2 < nk) { issue_stage(it + 2); cp_commit(); }

        const unsigned short* cA = smem_us + (it % 3) * STG_H;
        const unsigned short* cB = cA + SA_SZ;
        #pragma unroll
        for (int ks = 0; ks < 2; ks++) {
            const int k0 = ks * 16;
            unsigned af[4][4];
            #pragma unroll
            for (int mt = 0; mt < 4; mt++) {
                int r = wr*64 + mt*16 + gid;
                af[mt][0] = *(const unsigned*)&cA[ r     *SA_ST + k0 + tig*2    ];
                af[mt][1] = *(const unsigned*)&cA[(r + 8)*SA_ST + k0 + tig*2    ];
                af[mt][2] = *(const unsigned*)&cA[ r     *SA_ST + k0 + tig*2 + 8];
                af[mt][3] = *(const unsigned*)&cA[(r + 8)*SA_ST + k0 + tig*2 + 8];
            }
            unsigned bf[4][2];
            #pragma unroll
            for (int nt = 0; nt < 4; nt++) {
                int c = wc*32 + nt*8 + gid;
                bf[nt][0] = *(const unsigned*)&cB[c*SB_ST + k0 + tig*2    ];
                bf[nt][1] = *(const unsigned*)&cB[c*SB_ST + k0 + tig*2 + 8];
            }
            #pragma unroll
            for (int mt = 0; mt < 4; mt++)
                #pragma unroll
                for (int nt = 0; nt < 4; nt++) {
                    asm volatile(
                      "mma.sync.aligned.m16n8k16.row.col.f32.f16.f16.f32 "
                      "{%0,%1,%2,%3},{%4,%5,%6,%7},{%8,%9},{%0,%1,%2,%3};"
                      : "+f"(acc[mt][nt][0]), "+f"(acc[mt][nt][1]),
                        "+f"(acc[mt][nt][2]), "+f"(acc[mt][nt][3])
                      : "r"(af[mt][0]), "r"(af[mt][1]),
                        "r"(af[mt][2]), "r"(af[mt][3]),
                        "r"(bf[nt][0]), "r"(bf[nt][1]));
                }
        }
    }

    // epilogue
    #pragma unroll
    for (int mt = 0; mt < 4; mt++) {
        #pragma unroll
        for (int nt = 0; nt < 4; nt++) {
            int r0  = row0 + wr*64 + mt*16 + gid;
            int col = col0 + wc*32 + nt*8 + tig*2;
            if (col < M) {
                float2 bb = make_float2(0.f, 0.f);
                if (bias) bb = *(const float2*)&bias[col];
                #pragma unroll
                for (int half_i = 0; half_i < 2; half_i++) {
                    int row = r0 + half_i*8;
                    float vx = acc[mt][nt][half_i*2    ] + bb.x;
                    float vy = acc[mt][nt][half_i*2 + 1] + bb.y;
                    if (EPI == 1) {
                        vx = 0.5f * vx * (1.0f + erff(vx * 0.70710678118654752f));
                        vy = 0.5f * vy * (1.0f + erff(vy * 0.70710678118654752f));
                        *(__half2*)&out[(size_t)row * M + col] = __floats2half2_rn(vx, vy);
                    } else if (EPI == 2) {
                        float2 rr = *(const float2*)&res[(size_t)row * M + col];
                        *(float2*)&((float*)out)[(size_t)row * M + col] =
                            make_float2(vx + rr.x, vy + rr.y);
                    } else {
                        *(float2*)&((float*)out)[(size_t)row * M + col] =
                            make_float2(vx, vy);
                    }
                }
            }
        }
    }
}

// ---------------- fused outlook attention + fold (reads fused va buffer) ----------------
#define PR_ROW 12
#define PR_HEAD (K2*PR_ROW)            // 108
#define PR_WARP (HEADS*PR_HEAD)        // 648

__global__ void attn_fold_kernel(const float* __restrict__ va,
                                 __half* __restrict__ tmp)
{
    __shared__ float probs[8][PR_WARP];
    int warp = threadIdx.x >> 5;
    int lane = threadIdx.x & 31;
    int t = blockIdx.x * 8 + warp;
    int b  = t / (HH*WW);
    int pq = t % (HH*WW);
    int p = pq / WW, q = pq % WW;

    // ---- phase A: 54 softmax rows over 27 lanes (2 each) ----
    if (lane < 27) {
        #pragma unroll
        for (int rep = 0; rep < 2; rep++) {
            int rr = lane + rep*27;
            int head = rr / K2;
            int i    = rr - head*K2;
            int di = i / KW, dj = i - di*KW;
            int tp = p + 1 - di, tq = q + 1 - dj;
            float* dst = &probs[warp][head*PR_HEAD + i*PR_ROW];
            if ((unsigned)tp < (unsigned)HH && (unsigned)tq < (unsigned)WW) {
                int ts = (b*HH + tp) * WW + tq;
                const float* ar = va + (size_t)ts * MVA + CC + head*81 + i*K2;
                float vv[K2];
                float mx = -INFINITY;
                #pragma unroll
                for (int j = 0; j < K2; j++) { vv[j] = ar[j] * SCALE; mx = fmaxf(mx, vv[j]); }
                float s = 0.f;
                #pragma unroll
                for (int j = 0; j < K2; j++) { vv[j] = __expf(vv[j] - mx); s += vv[j]; }
                float inv = __fdividef(1.f, s);
                #pragma unroll
                for (int j = 0; j < K2; j++) dst[j] = vv[j] * inv;
            } else {
                #pragma unroll
                for (int j = 0; j < K2; j++) dst[j] = 0.f;
            }
        }
    }
    __syncwarp();

    // ---- phase B: window gather (v = first CC cols of va) ----
    int rowbase[5], coloff[5];
    unsigned rmask = 0, cmask = 0;
    #pragma unroll
    for (int d = 0; d < 5; d++) {
        int vp = p + d - 2, vq = q + d - 2;
        bool rok = (unsigned)vp < (unsigned)HH;
        bool cok = (unsigned)vq < (unsigned)WW;
        rowbase[d] = rok ? ((b*HH + vp) * WW) * MVA : 0;
        coloff[d]  = cok ? vq * MVA : 0;
        if (rok) rmask |= (1u << d);
        if (cok) cmask |= (1u << d);
    }

    for (int head = 0; head < HEADS; head++) {
        const int ch = head*HD + lane;
        float vr[25];
        #pragma unroll
        for (int dp = 0; dp < 5; dp++) {
            #pragma unroll
            for (int dq = 0; dq < 5; dq++) {
                bool ok = ((rmask >> dp) & 1u) && ((cmask >> dq) & 1u);
                vr[dp*5 + dq] = ok ? va[(size_t)(rowbase[dp] + coloff[dq] + ch)] : 0.f;
            }
        }
        const float* prh = &probs[warp][head*PR_HEAD];
        float acc = 0.f;
        #pragma unroll
        for (int i = 0; i < K2; i++) {
            int di = i / KW, dj = i - di*KW;
            const float4* rp = (const float4*)(prh + i*PR_ROW);
            float4 r0 = rp[0], r1 = rp[1];
            float  r2 = prh[i*PR_ROW + 8];
            float pr[K2] = {r0.x, r0.y, r0.z, r0.w, r1.x, r1.y, r1.z, r1.w, r2};
            const float* vb = &vr[(2 - di)*5 + (2 - dj)];
            #pragma unroll
            for (int j = 0; j < K2; j++) {
                int ei = j / KW, ej = j - ei*KW;
                acc = fmaf(pr[j], vb[ei*5 + ej], acc);
            }
        }
        tmp[(size_t)t * CC + ch] = __float2half_rn(acc);
    }
}

// ---------------- launcher ----------------
extern "C" void kernel_launch(void* const* d_in, const int* in_sizes, int n_in,
                              void* d_out, int out_size)
{
    const float* x     = (const float*)d_in[0];
    const float* ln1_g = (const float*)d_in[1];
    const float* ln1_b = (const float*)d_in[2];
    const float* Wv    = (const float*)d_in[3];
    const float* Wa    = (const float*)d_in[4];
    const float* ba    = (const float*)d_in[5];
    const float* Wp    = (const float*)d_in[6];
    const float* bp    = (const float*)d_in[7];
    const float* ln2_g = (const float*)d_in[8];
    const float* ln2_b = (const float*)d_in[9];
    const float* W1    = (const float*)d_in[10];
    const float* b1    = (const float*)d_in[11];
    const float* W2    = (const float*)d_in[12];
    const float* b2    = (const float*)d_in[13];
    float* out = (float*)d_out;

    __half *p_wh, *p_ln1, *p_tmp, *p_ln2, *p_h1;
    float  *p_bva, *p_va, *p_x2;
    cudaGetSymbolAddress((void**)&p_wh,  g_wh);
    cudaGetSymbolAddress((void**)&p_bva, g_bva);
    cudaGetSymbolAddress((void**)&p_ln1, g_ln1);
    cudaGetSymbolAddress((void**)&p_va,  g_va);
    cudaGetSymbolAddress((void**)&p_tmp, g_tmp);
    cudaGetSymbolAddress((void**)&p_x2,  g_x2);
    cudaGetSymbolAddress((void**)&p_ln2, g_ln2);
    cudaGetSymbolAddress((void**)&p_h1,  g_h1);

    cudaFuncSetAttribute((const void*)gemm_f16_kernel<0,float>,  cudaFuncAttributeMaxDynamicSharedMemorySize, GEMM_SMEM);
    cudaFuncSetAttribute((const void*)gemm_f16_kernel<1,__half>, cudaFuncAttributeMaxDynamicSharedMemorySize, GEMM_SMEM);
    cudaFuncSetAttribute((const void*)gemm_f16_kernel<2,float>,  cudaFuncAttributeMaxDynamicSharedMemorySize, GEMM_SMEM);

    const int RB = NTOK / 256;   // 98

    wconv_kernel<<<(N_WCONV + 255)/256, 256>>>(Wv, Wa, Wp, W1, W2, p_wh);
    bias_fuse_kernel<<<3, 256>>>(ba, p_bva);
    ln_kernel<<<NTOK/8, 256>>>(x, ln1_g, ln1_b, p_ln1);
    gemm_f16_kernel<0,float><<<dim3(11, RB), 256, GEMM_SMEM>>>(p_ln1, p_wh + WOFF_VA, p_bva, nullptr, p_va, CC, MVA);
    attn_fold_kernel<<<NTOK/8, 256>>>(p_va, p_tmp);
    gemm_f16_kernel<2,float><<<dim3(3, RB), 256, GEMM_SMEM>>>(p_tmp, p_wh + WOFF_P, bp, x, p_x2, CC, CC);
    ln_kernel<<<NTOK/8, 256>>>(p_x2, ln2_g, ln2_b, p_ln2);
    gemm_f16_kernel<1,__half><<<dim3(9, RB), 256, GEMM_SMEM>>>(p_ln2, p_wh + WOFF_1, b1, nullptr, p_h1, CC, HID);
    gemm_f16_kernel<2,float><<<dim3(3, RB), 256, GEMM_SMEM>>>(p_h1, p_wh + WOFF_2, b2, p_x2, out, HID, CC);
}